// round 6
// baseline (speedup 1.0000x reference)
#include <cuda_runtime.h>
#include <cuda_bf16.h>
#include <math.h>

// Problem constants
#define PB  32
#define PM  10
#define PN  1000
#define MN  1010          // M + N
#define PD  128
#define NODES_TOTAL (PB*MN*PD)   // 4,136,960

// k_main tiling: 8 warps/block, JPW j's per warp, agent dim split in 2
#define JPW 4
#define JPB (8*JPW)                       // 32 j's per block
#define JTILES ((MN + JPB - 1) / JPB)     // 32
#define IH  (PM/2)                        // 5 agents per block

// Scratch (device globals — no allocation allowed)
__device__ __align__(16) float g_vpref[PD];      // Wp @ W_pref[:,0]
__device__ __align__(16) float g_Wnc[PD*5];      // Wn @ W_clients (128x5)
__device__ __align__(16) float g_Wna[PD*4];      // Wn @ W_agents  (128x4)
__device__ __align__(16) float g_A[PB*PM*PD];    // agent broadcast term (B*M x 128)

// ---------------------------------------------------------------------------
// Prologue kernel: 480 blocks x 256 threads.
//  [0,160)   : weight folds (one warp per dot-128 output: vpref / Wnc / Wna)
//  [160,480) : per-(b,i) agent A-chain -> g_A
// ---------------------------------------------------------------------------
__global__ void __launch_bounds__(256) k_pre(
                      const float* __restrict__ Wpp,    // W_posproj (128x128)
                      const float* __restrict__ alpha,  // (1,)
                      const float* __restrict__ Wfin,   // W_final (128x384)
                      const float* __restrict__ Wpref,  // W_pref (128x1)
                      const float* __restrict__ Wc,     // W_clients (128x5)
                      const float* __restrict__ Wa,     // W_agents (128x4)
                      const float* __restrict__ locs,   // (B,1010,2)
                      const float* __restrict__ cap,    // (B,10)
                      const float* __restrict__ spd,    // (B,10)
                      const float* __restrict__ Wdep,   // W_depot (128x2)
                      const float* __restrict__ Wda)    // W_depot_agents (128x256)
{
    const int lane = threadIdx.x & 31;
    const int warp = threadIdx.x >> 5;    // 0..7

    if (blockIdx.x < 160) {
        // ---------------- weight folds ----------------
        const int t = blockIdx.x * 8 + warp;
        float s = 0.f;
        if (t < 128) {
            const int d1 = t;
            #pragma unroll
            for (int q = 0; q < 4; q++) {
                int e = lane + 32 * q;
                s += Wfin[d1 * 384 + 128 + e] * Wpref[e];
            }
            #pragma unroll
            for (int o = 16; o; o >>= 1) s += __shfl_xor_sync(0xffffffffu, s, o);
            if (lane == 0) g_vpref[d1] = s;
        } else if (t < 768) {
            const int o = t - 128, d1 = o / 5, k = o % 5;
            #pragma unroll
            for (int q = 0; q < 4; q++) {
                int e = lane + 32 * q;
                s += Wfin[d1 * 384 + e] * __ldg(&Wc[e * 5 + k]);
            }
            #pragma unroll
            for (int off = 16; off; off >>= 1) s += __shfl_xor_sync(0xffffffffu, s, off);
            if (lane == 0) g_Wnc[o] = s;
        } else {
            const int o = t - 768, d1 = o / 4, k = o % 4;
            #pragma unroll
            for (int q = 0; q < 4; q++) {
                int e = lane + 32 * q;
                s += Wfin[d1 * 384 + e] * __ldg(&Wa[e * 4 + k]);
            }
            #pragma unroll
            for (int off = 16; off; off >>= 1) s += __shfl_xor_sync(0xffffffffu, s, off);
            if (lane == 0) g_Wna[o] = s;
        }
        return;
    }

    // ---------------- agent A-chain: one block per (b, i) ----------------
    const int idx = blockIdx.x - 160;     // 0..319
    const int b = idx / PM;
    const int i = idx % PM;
    const int tid = threadIdx.x;

    __shared__ float spe[PD], sde[PD], sae[PD], sdA[PD];

    const float lx = __ldg(&locs[(b * MN + i) * 2 + 0]);
    const float ly = __ldg(&locs[(b * MN + i) * 2 + 1]);
    const float c  = __ldg(&cap[b * PM + i]) * (1.0f / 40.0f);
    const float sp = __ldg(&spd[b * PM + i]);

    if (tid < PD) {
        sae[tid] = lx * Wa[tid * 4 + 0] + ly * Wa[tid * 4 + 1]
                 + c  * Wa[tid * 4 + 2] + sp * Wa[tid * 4 + 3];
        const float nl = -logf(10000.0f) / (float)PD;
        int k2 = (tid >> 1) * 2;
        float ang = (float)i * expf((float)k2 * nl);
        spe[tid] = (tid & 1) ? cosf(ang) : sinf(ang);
    }
    __syncthreads();

    const float a0 = __ldg(&alpha[0]);
    for (int r = 0; r < 16; r++) {
        int d1 = warp * 16 + r;
        float s = 0.f;
        #pragma unroll
        for (int q = 0; q < 4; q++) {
            int e = lane + 32 * q;
            s += spe[e] * Wpp[d1 * PD + e];
        }
        #pragma unroll
        for (int off = 16; off; off >>= 1) s += __shfl_xor_sync(0xffffffffu, s, off);
        if (lane == 0)
            sde[d1] = lx * Wdep[d1 * 2 + 0] + ly * Wdep[d1 * 2 + 1] + a0 * s;
    }
    __syncthreads();

    for (int r = 0; r < 16; r++) {
        int d1 = warp * 16 + r;
        float s = 0.f;
        #pragma unroll
        for (int q = 0; q < 4; q++) {
            int e = lane + 32 * q;
            s += sde[e] * Wda[d1 * 256 + e] + sae[e] * Wda[d1 * 256 + 128 + e];
        }
        #pragma unroll
        for (int off = 16; off; off >>= 1) s += __shfl_xor_sync(0xffffffffu, s, off);
        if (lane == 0) sdA[d1] = s;
    }
    __syncthreads();

    for (int r = 0; r < 16; r++) {
        int d1 = warp * 16 + r;
        float s = 0.f;
        #pragma unroll
        for (int q = 0; q < 4; q++) {
            int e = lane + 32 * q;
            s += sdA[e] * Wfin[d1 * 384 + 256 + e];
        }
        #pragma unroll
        for (int off = 16; off; off >>= 1) s += __shfl_xor_sync(0xffffffffu, s, off);
        if (lane == 0) g_A[(b * PM + i) * PD + d1] = s;
    }
}

// ---------------------------------------------------------------------------
// Main kernel. grid = (JTILES=32, PB=32, 2); block = 256 (8 warps).
// blockIdx.z selects agents [i0, i0+5). Each thread keeps 5 A-rows (float4),
// v_pref, and folded Wnc in registers. Features computed inline per warp-j.
// igrp==0 block also emits the nodes_embedding row.
// Hot loop per j: ~8 scalar LDG + ~20 FMA + 5-6 STG.128 streaming stores.
// ---------------------------------------------------------------------------
__global__ void __launch_bounds__(256) k_main(
                       const float* __restrict__ locs,    // (B,1010,2)
                       const float* __restrict__ cap,     // (B,10)
                       const float* __restrict__ spd,     // (B,10)
                       const float* __restrict__ demand,  // (B,1,1010)
                       const float* __restrict__ pref,    // (B,10,1010)
                       const float* __restrict__ Wa,      // W_agents (128x4)
                       const float* __restrict__ Wc,      // W_clients (128x5)
                       float* __restrict__ out)
{
    const int b    = blockIdx.y;
    const int jt   = blockIdx.x;
    const int i0   = blockIdx.z * IH;      // 0 or 5
    const int lane = threadIdx.x & 31;
    const int warp = threadIdx.x >> 5;
    const int d0   = lane * 4;

    // Register state
    const float4 vp = *reinterpret_cast<const float4*>(&g_vpref[d0]);

    float wnc[4][5];
    #pragma unroll
    for (int r = 0; r < 4; r++)
        #pragma unroll
        for (int k = 0; k < 5; k++)
            wnc[r][k] = g_Wnc[(d0 + r) * 5 + k];

    float4 a[IH];
    #pragma unroll
    for (int i = 0; i < IH; i++)
        a[i] = *reinterpret_cast<const float4*>(&g_A[(b * PM + i0 + i) * PD + d0]);

    const float depx = __ldg(&locs[b * MN * 2 + 0]);
    const float depy = __ldg(&locs[b * MN * 2 + 1]);

    float* __restrict__ out2 = out + NODES_TOTAL;

    #pragma unroll
    for (int t = 0; t < JPW; t++) {
        const int j = jt * JPB + warp + 8 * t;
        if (j >= MN) break;

        const float lx = __ldg(&locs[(b * MN + j) * 2 + 0]);
        const float ly = __ldg(&locs[(b * MN + j) * 2 + 1]);

        float nw[4];
        float ne[4];

        if (j < PM) {
            const float c  = __ldg(&cap[b * PM + j]) * (1.0f / 40.0f);
            const float sp = __ldg(&spd[b * PM + j]);
            #pragma unroll
            for (int r = 0; r < 4; r++) {
                const int d = d0 + r;
                nw[r] = lx * __ldg(&g_Wna[d * 4 + 0]) + ly * __ldg(&g_Wna[d * 4 + 1])
                      + c  * __ldg(&g_Wna[d * 4 + 2]) + sp * __ldg(&g_Wna[d * 4 + 3]);
                if (i0 == 0)
                    ne[r] = lx * __ldg(&Wa[d * 4 + 0]) + ly * __ldg(&Wa[d * 4 + 1])
                          + c  * __ldg(&Wa[d * 4 + 2]) + sp * __ldg(&Wa[d * 4 + 3]);
            }
        } else {
            const float dx   = lx - depx;
            const float dy   = ly - depy;
            const float dist = sqrtf(dx * dx + dy * dy);
            const float ang  = atan2f(dy, dx);
            const float dem  = __ldg(&demand[b * MN + j]) * (1.0f / 40.0f);
            #pragma unroll
            for (int r = 0; r < 4; r++) {
                nw[r] = lx * wnc[r][0] + ly * wnc[r][1] + dem * wnc[r][2]
                      + dist * wnc[r][3] + ang * wnc[r][4];
                if (i0 == 0) {
                    const int d = d0 + r;
                    ne[r] = lx  * __ldg(&Wc[d * 5 + 0]) + ly   * __ldg(&Wc[d * 5 + 1])
                          + dem * __ldg(&Wc[d * 5 + 2]) + dist * __ldg(&Wc[d * 5 + 3])
                          + ang * __ldg(&Wc[d * 5 + 4]);
                }
            }
        }

        if (i0 == 0)
            __stcs(reinterpret_cast<float4*>(&out[(b * MN + j) * PD + d0]),
                   make_float4(ne[0], ne[1], ne[2], ne[3]));

        float p[IH];
        #pragma unroll
        for (int i = 0; i < IH; i++)
            p[i] = __ldg(&pref[(b * PM + i0 + i) * MN + j]);

        #pragma unroll
        for (int i = 0; i < IH; i++) {
            float4 v;
            v.x = nw[0] + p[i] * vp.x + a[i].x;
            v.y = nw[1] + p[i] * vp.y + a[i].y;
            v.z = nw[2] + p[i] * vp.z + a[i].z;
            v.w = nw[3] + p[i] * vp.w + a[i].w;
            __stcs(reinterpret_cast<float4*>(
                       &out2[((b * PM + i0 + i) * MN + j) * PD + d0]), v);
        }
    }
}

// ---------------------------------------------------------------------------
extern "C" void kernel_launch(void* const* d_in, const int* in_sizes, int n_in,
                              void* d_out, int out_size)
{
    const float* locs      = (const float*)d_in[0];
    const float* capacity  = (const float*)d_in[1];
    const float* speed     = (const float*)d_in[2];
    const float* demand    = (const float*)d_in[3];
    const float* pref      = (const float*)d_in[4];
    // d_in[5] = action_mask (bool) — unused
    const float* W_depot   = (const float*)d_in[6];
    const float* W_posproj = (const float*)d_in[7];
    const float* alpha     = (const float*)d_in[8];
    const float* W_agents  = (const float*)d_in[9];
    const float* W_da      = (const float*)d_in[10];
    const float* W_clients = (const float*)d_in[11];
    const float* W_pref    = (const float*)d_in[12];
    const float* W_final   = (const float*)d_in[13];
    float* out = (float*)d_out;

    k_pre<<<480, 256>>>(W_posproj, alpha, W_final, W_pref, W_clients, W_agents,
                        locs, capacity, speed, W_depot, W_da);

    dim3 grid(JTILES, PB, 2);
    k_main<<<grid, 256>>>(locs, capacity, speed, demand, pref,
                          W_agents, W_clients, out);
}

// round 7
// speedup vs baseline: 1.5324x; 1.5324x over previous
#include <cuda_runtime.h>
#include <cuda_bf16.h>
#include <math.h>

// Problem constants
#define PB  32
#define PM  10
#define PN  1000
#define MN  1010          // M + N
#define PD  128
#define NODES_TOTAL (PB*MN*PD)   // 4,136,960

// k_comb tiling: 8 warps/block, JPW j's per warp
#define JPW 6
#define JPB (8*JPW)                       // 48 j's per block
#define JTILES ((MN + JPB - 1) / JPB)     // 22

// Scratch (device globals — no allocation allowed)
__device__ __align__(16) float g_vpref[PD];      // Wp @ W_pref[:,0]
__device__ __align__(16) float g_Wnc[PD*5];      // Wn @ W_clients (128x5)
__device__ __align__(16) float g_Wna[PD*4];      // Wn @ W_agents  (128x4)
__device__ __align__(16) float g_A[PB*PM*PD];    // agent broadcast term (B*M x 128)

// ---------------------------------------------------------------------------
// Prologue kernel: 480 blocks x 256 threads.
//  [0,160)   : weight folds (one warp per dot-128 output: vpref / Wnc / Wna)
//  [160,480) : per-(b,i) agent A-chain -> g_A
// ---------------------------------------------------------------------------
__global__ void __launch_bounds__(256) k_pre(
                      const float* __restrict__ Wpp,    // W_posproj (128x128)
                      const float* __restrict__ alpha,  // (1,)
                      const float* __restrict__ Wfin,   // W_final (128x384)
                      const float* __restrict__ Wpref,  // W_pref (128x1)
                      const float* __restrict__ Wc,     // W_clients (128x5)
                      const float* __restrict__ Wa,     // W_agents (128x4)
                      const float* __restrict__ locs,   // (B,1010,2)
                      const float* __restrict__ cap,    // (B,10)
                      const float* __restrict__ spd,    // (B,10)
                      const float* __restrict__ Wdep,   // W_depot (128x2)
                      const float* __restrict__ Wda)    // W_depot_agents (128x256)
{
    const int lane = threadIdx.x & 31;
    const int warp = threadIdx.x >> 5;    // 0..7

    if (blockIdx.x < 160) {
        // ---------------- weight folds ----------------
        const int t = blockIdx.x * 8 + warp;
        float s = 0.f;
        if (t < 128) {
            const int d1 = t;
            #pragma unroll
            for (int q = 0; q < 4; q++) {
                int e = lane + 32 * q;
                s += Wfin[d1 * 384 + 128 + e] * Wpref[e];
            }
            #pragma unroll
            for (int o = 16; o; o >>= 1) s += __shfl_xor_sync(0xffffffffu, s, o);
            if (lane == 0) g_vpref[d1] = s;
        } else if (t < 768) {
            const int o = t - 128, d1 = o / 5, k = o % 5;
            #pragma unroll
            for (int q = 0; q < 4; q++) {
                int e = lane + 32 * q;
                s += Wfin[d1 * 384 + e] * __ldg(&Wc[e * 5 + k]);
            }
            #pragma unroll
            for (int off = 16; off; off >>= 1) s += __shfl_xor_sync(0xffffffffu, s, off);
            if (lane == 0) g_Wnc[o] = s;
        } else {
            const int o = t - 768, d1 = o / 4, k = o % 4;
            #pragma unroll
            for (int q = 0; q < 4; q++) {
                int e = lane + 32 * q;
                s += Wfin[d1 * 384 + e] * __ldg(&Wa[e * 4 + k]);
            }
            #pragma unroll
            for (int off = 16; off; off >>= 1) s += __shfl_xor_sync(0xffffffffu, s, off);
            if (lane == 0) g_Wna[o] = s;
        }
        return;
    }

    // ---------------- agent A-chain: one block per (b, i) ----------------
    const int idx = blockIdx.x - 160;     // 0..319
    const int b = idx / PM;
    const int i = idx % PM;
    const int tid = threadIdx.x;

    __shared__ float spe[PD], sde[PD], sae[PD], sdA[PD];

    const float lx = __ldg(&locs[(b * MN + i) * 2 + 0]);
    const float ly = __ldg(&locs[(b * MN + i) * 2 + 1]);
    const float c  = __ldg(&cap[b * PM + i]) * (1.0f / 40.0f);
    const float sp = __ldg(&spd[b * PM + i]);

    if (tid < PD) {
        sae[tid] = lx * Wa[tid * 4 + 0] + ly * Wa[tid * 4 + 1]
                 + c  * Wa[tid * 4 + 2] + sp * Wa[tid * 4 + 3];
        const float nl = -logf(10000.0f) / (float)PD;
        int k2 = (tid >> 1) * 2;
        float ang = (float)i * expf((float)k2 * nl);
        spe[tid] = (tid & 1) ? cosf(ang) : sinf(ang);
    }
    __syncthreads();

    const float a0 = __ldg(&alpha[0]);
    for (int r = 0; r < 16; r++) {
        int d1 = warp * 16 + r;
        float s = 0.f;
        #pragma unroll
        for (int q = 0; q < 4; q++) {
            int e = lane + 32 * q;
            s += spe[e] * Wpp[d1 * PD + e];
        }
        #pragma unroll
        for (int off = 16; off; off >>= 1) s += __shfl_xor_sync(0xffffffffu, s, off);
        if (lane == 0)
            sde[d1] = lx * Wdep[d1 * 2 + 0] + ly * Wdep[d1 * 2 + 1] + a0 * s;
    }
    __syncthreads();

    for (int r = 0; r < 16; r++) {
        int d1 = warp * 16 + r;
        float s = 0.f;
        #pragma unroll
        for (int q = 0; q < 4; q++) {
            int e = lane + 32 * q;
            s += sde[e] * Wda[d1 * 256 + e] + sae[e] * Wda[d1 * 256 + 128 + e];
        }
        #pragma unroll
        for (int off = 16; off; off >>= 1) s += __shfl_xor_sync(0xffffffffu, s, off);
        if (lane == 0) sdA[d1] = s;
    }
    __syncthreads();

    for (int r = 0; r < 16; r++) {
        int d1 = warp * 16 + r;
        float s = 0.f;
        #pragma unroll
        for (int q = 0; q < 4; q++) {
            int e = lane + 32 * q;
            s += sdA[e] * Wfin[d1 * 384 + 256 + e];
        }
        #pragma unroll
        for (int off = 16; off; off >>= 1) s += __shfl_xor_sync(0xffffffffu, s, off);
        if (lane == 0) g_A[(b * PM + i) * PD + d1] = s;
    }
}

// ---------------------------------------------------------------------------
// Combined-embedding + nodes-embedding kernel.
// grid = (JTILES=22, PB=32); block = 256 (8 warps). Each thread keeps all 10
// A-rows (float4), v_pref, and folded Wnc in registers. Features (dist/angle/
// dem) computed inline once per warp-j. Hot loop per j: ~8 scalar LDG,
// ~35 FMA + MUFU, 11 STG.128 streaming stores. No shared memory.
// ---------------------------------------------------------------------------
__global__ void __launch_bounds__(256) k_comb(
                       const float* __restrict__ locs,    // (B,1010,2)
                       const float* __restrict__ cap,     // (B,10)
                       const float* __restrict__ spd,     // (B,10)
                       const float* __restrict__ demand,  // (B,1,1010)
                       const float* __restrict__ pref,    // (B,10,1010)
                       const float* __restrict__ Wa,      // W_agents (128x4)
                       const float* __restrict__ Wc,      // W_clients (128x5)
                       float* __restrict__ out)
{
    const int b    = blockIdx.y;
    const int jt   = blockIdx.x;
    const int lane = threadIdx.x & 31;
    const int warp = threadIdx.x >> 5;
    const int d0   = lane * 4;

    // Per-thread register state
    const float4 vp = *reinterpret_cast<const float4*>(&g_vpref[d0]);

    float wnc[4][5];
    #pragma unroll
    for (int r = 0; r < 4; r++)
        #pragma unroll
        for (int k = 0; k < 5; k++)
            wnc[r][k] = g_Wnc[(d0 + r) * 5 + k];

    float4 a[PM];
    #pragma unroll
    for (int i = 0; i < PM; i++)
        a[i] = *reinterpret_cast<const float4*>(&g_A[(b * PM + i) * PD + d0]);

    const float depx = __ldg(&locs[b * MN * 2 + 0]);
    const float depy = __ldg(&locs[b * MN * 2 + 1]);

    float* __restrict__ out2 = out + NODES_TOTAL;

    #pragma unroll
    for (int t = 0; t < JPW; t++) {
        const int j = jt * JPB + warp + 8 * t;
        if (j >= MN) break;

        const float lx = __ldg(&locs[(b * MN + j) * 2 + 0]);
        const float ly = __ldg(&locs[(b * MN + j) * 2 + 1]);

        float nw[4], ne[4];

        if (j < PM) {
            // agent node: feats = [x, y, cap/40, speed]
            const float c  = __ldg(&cap[b * PM + j]) * (1.0f / 40.0f);
            const float sp = __ldg(&spd[b * PM + j]);
            #pragma unroll
            for (int r = 0; r < 4; r++) {
                const int d = d0 + r;
                nw[r] = lx * __ldg(&g_Wna[d * 4 + 0]) + ly * __ldg(&g_Wna[d * 4 + 1])
                      + c  * __ldg(&g_Wna[d * 4 + 2]) + sp * __ldg(&g_Wna[d * 4 + 3]);
                ne[r] = lx * __ldg(&Wa[d * 4 + 0]) + ly * __ldg(&Wa[d * 4 + 1])
                      + c  * __ldg(&Wa[d * 4 + 2]) + sp * __ldg(&Wa[d * 4 + 3]);
            }
        } else {
            // client node: feats = [x, y, dem/40, dist, angle]
            const float dx   = lx - depx;
            const float dy   = ly - depy;
            const float dist = sqrtf(dx * dx + dy * dy);
            const float ang  = atan2f(dy, dx);
            const float dem  = __ldg(&demand[b * MN + j]) * (1.0f / 40.0f);
            #pragma unroll
            for (int r = 0; r < 4; r++) {
                nw[r] = lx * wnc[r][0] + ly * wnc[r][1] + dem * wnc[r][2]
                      + dist * wnc[r][3] + ang * wnc[r][4];
                const int d = d0 + r;
                ne[r] = lx  * __ldg(&Wc[d * 5 + 0]) + ly   * __ldg(&Wc[d * 5 + 1])
                      + dem * __ldg(&Wc[d * 5 + 2]) + dist * __ldg(&Wc[d * 5 + 3])
                      + ang * __ldg(&Wc[d * 5 + 4]);
            }
        }

        // nodes_embedding row
        __stcs(reinterpret_cast<float4*>(&out[(b * MN + j) * PD + d0]),
               make_float4(ne[0], ne[1], ne[2], ne[3]));

        // prefetch pref scalars (independent broadcast loads)
        float p[PM];
        #pragma unroll
        for (int i = 0; i < PM; i++)
            p[i] = __ldg(&pref[(b * PM + i) * MN + j]);

        #pragma unroll
        for (int i = 0; i < PM; i++) {
            float4 v;
            v.x = nw[0] + p[i] * vp.x + a[i].x;
            v.y = nw[1] + p[i] * vp.y + a[i].y;
            v.z = nw[2] + p[i] * vp.z + a[i].z;
            v.w = nw[3] + p[i] * vp.w + a[i].w;
            __stcs(reinterpret_cast<float4*>(
                       &out2[((b * PM + i) * MN + j) * PD + d0]), v);
        }
    }
}

// ---------------------------------------------------------------------------
extern "C" void kernel_launch(void* const* d_in, const int* in_sizes, int n_in,
                              void* d_out, int out_size)
{
    const float* locs      = (const float*)d_in[0];
    const float* capacity  = (const float*)d_in[1];
    const float* speed     = (const float*)d_in[2];
    const float* demand    = (const float*)d_in[3];
    const float* pref      = (const float*)d_in[4];
    // d_in[5] = action_mask (bool) — unused
    const float* W_depot   = (const float*)d_in[6];
    const float* W_posproj = (const float*)d_in[7];
    const float* alpha     = (const float*)d_in[8];
    const float* W_agents  = (const float*)d_in[9];
    const float* W_da      = (const float*)d_in[10];
    const float* W_clients = (const float*)d_in[11];
    const float* W_pref    = (const float*)d_in[12];
    const float* W_final   = (const float*)d_in[13];
    float* out = (float*)d_out;

    k_pre<<<480, 256>>>(W_posproj, alpha, W_final, W_pref, W_clients, W_agents,
                        locs, capacity, speed, W_depot, W_da);

    dim3 grid(JTILES, PB);
    k_comb<<<grid, 256>>>(locs, capacity, speed, demand, pref,
                          W_agents, W_clients, out);
}